// round 1
// baseline (speedup 1.0000x reference)
#include <cuda_runtime.h>
#include <math.h>

// Problem constants (fixed by the dataset)
#define BB   2
#define LL   4096
#define HH   16
#define MM   64
#define DMODEL 1024
#define NROWS (BB*LL*HH)          // 131072 (b,l,h) rows of 64 features
#define DN    0.3535533905932738f // 64^{-1/4}
#define DIAGC 0.0625f             // 0.5*dn*dn
#define INVSQRTM 0.125f           // 1/sqrt(64)

// Scratch (static device arrays; no allocation allowed)
__device__ float g_q[BB*LL*DMODEL];
__device__ float g_k[BB*LL*DMODEL];
__device__ float g_v[BB*LL*DMODEL];
__device__ float g_o[BB*LL*DMODEL];
__device__ float g_kmax[BB*HH];

// ---------------------------------------------------------------------------
// SGEMM: C[M,N] = A[M,K] @ W[K,N] + bias[N]   (row-major, fp32)
// 128x128 tile, BK=8, 256 threads, 8x8 per thread.
// Assumes M%128==0, N%128==0, K%8==0 (true for all calls here).
// ---------------------------------------------------------------------------
#define GBM 128
#define GBN 128
#define GBK 8

__global__ __launch_bounds__(256, 2)
void sgemm_bias(const float* __restrict__ A, const float* __restrict__ W,
                const float* __restrict__ bias, float* __restrict__ C,
                int M, int N, int K)
{
    __shared__ float As[GBK][GBM];
    __shared__ float Ws[GBK][GBN];

    const int tid = threadIdx.x;
    const int bm = blockIdx.y * GBM;
    const int bn = blockIdx.x * GBN;

    // A tile load: 128x8 floats = one float4 per thread
    const int a_row = tid >> 1;          // 0..127
    const int a_col = (tid & 1) * 4;     // 0 or 4
    // W tile load: 8x128 floats = one float4 per thread
    const int w_row = tid >> 5;          // 0..7
    const int w_col = (tid & 31) * 4;    // 0..124

    const int tx = tid & 15;             // col group
    const int ty = tid >> 4;             // row group

    float acc[8][8];
#pragma unroll
    for (int i = 0; i < 8; i++)
#pragma unroll
        for (int j = 0; j < 8; j++) acc[i][j] = 0.f;

    const float* Aptr = A + (size_t)(bm + a_row) * K + a_col;
    const float* Wptr = W + (size_t)w_row * N + bn + w_col;

    for (int k0 = 0; k0 < K; k0 += GBK) {
        float4 av = *(const float4*)(Aptr + k0);
        As[a_col + 0][a_row] = av.x;
        As[a_col + 1][a_row] = av.y;
        As[a_col + 2][a_row] = av.z;
        As[a_col + 3][a_row] = av.w;
        float4 wv = *(const float4*)(Wptr + (size_t)k0 * N);
        *(float4*)&Ws[w_row][w_col] = wv;
        __syncthreads();

#pragma unroll
        for (int k = 0; k < GBK; k++) {
            float af[8], wf[8];
            *(float4*)&af[0] = *(const float4*)&As[k][ty * 8];
            *(float4*)&af[4] = *(const float4*)&As[k][ty * 8 + 4];
            *(float4*)&wf[0] = *(const float4*)&Ws[k][tx * 8];
            *(float4*)&wf[4] = *(const float4*)&Ws[k][tx * 8 + 4];
#pragma unroll
            for (int i = 0; i < 8; i++)
#pragma unroll
                for (int j = 0; j < 8; j++)
                    acc[i][j] = fmaf(af[i], wf[j], acc[i][j]);
        }
        __syncthreads();
    }

    // epilogue: add bias, write
    float bvals[8];
#pragma unroll
    for (int j = 0; j < 8; j++) bvals[j] = bias[bn + tx * 8 + j];

#pragma unroll
    for (int i = 0; i < 8; i++) {
        float* crow = C + (size_t)(bm + ty * 8 + i) * N + bn + tx * 8;
        float4 o0, o1;
        o0.x = acc[i][0] + bvals[0]; o0.y = acc[i][1] + bvals[1];
        o0.z = acc[i][2] + bvals[2]; o0.w = acc[i][3] + bvals[3];
        o1.x = acc[i][4] + bvals[4]; o1.y = acc[i][5] + bvals[5];
        o1.z = acc[i][6] + bvals[6]; o1.w = acc[i][7] + bvals[7];
        *(float4*)(crow)     = o0;
        *(float4*)(crow + 4) = o1;
    }
}

// ---------------------------------------------------------------------------
// kmax: per (b,h), max over (l,m) of (dn * k_proj)
// ---------------------------------------------------------------------------
__global__ void kmax_kernel(const float* __restrict__ Kp, float* __restrict__ kmax)
{
    const int bh = blockIdx.x;       // 0..31
    const int b = bh >> 4, h = bh & 15;
    const int tid = threadIdx.x;     // 256
    float m = -1e30f;
    // elements: Kp[((b*LL+l)*HH+h)*64 + mm]
    for (int idx = tid; idx < LL * MM; idx += 256) {
        int l = idx >> 6, mm = idx & 63;
        float v = Kp[((size_t)(b * LL + l) * HH + h) * MM + mm];
        m = fmaxf(m, v);
    }
    __shared__ float red[256];
    red[tid] = m;
    __syncthreads();
    for (int s = 128; s > 0; s >>= 1) {
        if (tid < s) red[tid] = fmaxf(red[tid], red[tid + s]);
        __syncthreads();
    }
    if (tid == 0) kmax[bh] = DN * red[0];
}

// ---------------------------------------------------------------------------
// FAVOR feature map (in-place): phi = 1/sqrt(M) * exp(W@X - diag - mx + 1e-8)
// X = dn * x;  diag = 0.5*dn^2 * ||X||^2
// query: mx = max_m X[m];  key: mx = kmax[b,h]
// 512 threads = 8 rows per pass, 8 passes = 64 rows per block. grid = 2048.
// ---------------------------------------------------------------------------
__global__ __launch_bounds__(512)
void favor_kernel(float* __restrict__ X, const float* __restrict__ Wf,
                  const float* __restrict__ kmax, int is_query)
{
    __shared__ float Wt[64][65];  // transposed: Wt[m][d] = Wf[d*64+m]
    __shared__ float xs[8][64];

    const int tid = threadIdx.x;
    for (int i = tid; i < 64 * 64; i += 512) {
        int d = i >> 6, m = i & 63;
        Wt[m][d] = Wf[i];
    }
    __syncthreads();

    const int r = tid >> 6;    // row within pass, 0..7
    const int d = tid & 63;

    for (int pass = 0; pass < 8; pass++) {
        int row = blockIdx.x * 64 + pass * 8 + r;   // (b,l,h) flat row
        xs[r][d] = DN * X[(size_t)row * 64 + d];
        __syncthreads();

        float dot = 0.f, ss = 0.f, mx = -1e30f;
#pragma unroll 8
        for (int m = 0; m < 64; m++) {
            float x = xs[r][m];
            dot = fmaf(Wt[m][d], x, dot);
            ss  = fmaf(x, x, ss);
            mx  = fmaxf(mx, x);
        }
        float mq;
        if (is_query) {
            mq = mx;
        } else {
            int h = row & 15;
            int b = row >> 16;   // row / (LL*HH) = row / 65536
            mq = kmax[b * HH + h];
        }
        float phi = INVSQRTM * __expf(dot - DIAGC * ss - mq + 1e-8f);
        __syncthreads();   // all reads of xs done before next pass overwrites
        X[(size_t)row * 64 + d] = phi;
    }
}

// ---------------------------------------------------------------------------
// Causal linear-attention scan. One CTA per (b,h). 256 threads.
// State S[64][64] in registers (16 cells / thread), snorm[64] in registers
// of threads tid<64. Double-buffered q/k/v rows + global prefetch.
// ---------------------------------------------------------------------------
__global__ __launch_bounds__(256, 1)
void scan_kernel(const float* __restrict__ Q, const float* __restrict__ Kp,
                 const float* __restrict__ V, float* __restrict__ Out)
{
    __shared__ __align__(16) float qs[2][64];
    __shared__ __align__(16) float ks[2][64];
    __shared__ __align__(16) float vs[2][64];
    __shared__ float part[4][64];
    __shared__ float pden[64];
    __shared__ float den_s;

    const int tid = threadIdx.x;
    const int d = tid & 63;
    const int g = tid >> 6;          // 0..3 : m-range [16g,16g+16)

    const int bh = blockIdx.x;
    const int b = bh >> 4, h = bh & 15;
    const size_t base = ((size_t)b * LL * HH + h) * MM;
    const size_t stride = HH * MM;   // 1024

    float S[16];
#pragma unroll
    for (int j = 0; j < 16; j++) S[j] = 0.f;
    float snorm = 0.f;

    // prefetch row 0
    const int role = g;              // 0:q 1:k 2:v 3:idle
    const float* src = (role == 0) ? Q : (role == 1) ? Kp : V;
    float rv = (role < 3) ? src[base + d] : 0.f;

    int cur = 0;
    for (int l = 0; l < LL; l++) {
        if (role == 0)      qs[cur][d] = rv;
        else if (role == 1) ks[cur][d] = rv;
        else if (role == 2) vs[cur][d] = rv;
        __syncthreads();

        // prefetch next row (latency hidden by compute)
        if (role < 3 && l + 1 < LL)
            rv = src[base + (size_t)(l + 1) * stride + d];

        // compute: S += k (outer) v ; p = partial of q^T S (over this m-range)
        float vd = vs[cur][d];
        float kf[16], qf[16];
#pragma unroll
        for (int jj = 0; jj < 4; jj++) {
            *(float4*)&kf[jj * 4] = *(const float4*)&ks[cur][g * 16 + jj * 4];
            *(float4*)&qf[jj * 4] = *(const float4*)&qs[cur][g * 16 + jj * 4];
        }
        float p = 0.f;
#pragma unroll
        for (int j = 0; j < 16; j++) {
            S[j] = fmaf(kf[j], vd, S[j]);
            p = fmaf(S[j], qf[j], p);
        }
        part[g][d] = p;
        if (tid < 64) {
            snorm += ks[cur][d];
            pden[d] = qs[cur][d] * snorm;
        }
        __syncthreads();

        if (tid < 32) {
            float t = pden[tid] + pden[tid + 32];
#pragma unroll
            for (int o = 16; o > 0; o >>= 1)
                t += __shfl_xor_sync(0xffffffffu, t, o);
            if (tid == 0) den_s = t;
        }
        __syncthreads();

        if (tid < 64) {
            float num = part[0][d] + part[1][d] + part[2][d] + part[3][d];
            Out[base + (size_t)l * stride + d] = num / den_s;
        }
        cur ^= 1;
    }
}

// ---------------------------------------------------------------------------
// Launch
// ---------------------------------------------------------------------------
extern "C" void kernel_launch(void* const* d_in, const int* in_sizes, int n_in,
                              void* d_out, int out_size)
{
    const float* queries = (const float*)d_in[0];
    const float* keys    = (const float*)d_in[1];
    const float* values  = (const float*)d_in[2];
    const float* Wq = (const float*)d_in[3];
    const float* bq = (const float*)d_in[4];
    const float* Wk = (const float*)d_in[5];
    const float* bk = (const float*)d_in[6];
    const float* Wv = (const float*)d_in[7];
    const float* bv = (const float*)d_in[8];
    const float* Wo = (const float*)d_in[9];
    const float* bo = (const float*)d_in[10];
    const float* Wfq = (const float*)d_in[11];
    const float* Wfk = (const float*)d_in[12];
    float* out = (float*)d_out;

    float *gq, *gk, *gv, *go, *gkm;
    cudaGetSymbolAddress((void**)&gq, g_q);
    cudaGetSymbolAddress((void**)&gk, g_k);
    cudaGetSymbolAddress((void**)&gv, g_v);
    cudaGetSymbolAddress((void**)&go, g_o);
    cudaGetSymbolAddress((void**)&gkm, g_kmax);

    const int Mrows = BB * LL;        // 8192
    dim3 ggrid(DMODEL / GBN, Mrows / GBM);  // (8, 64)

    // 1-3: projections
    sgemm_bias<<<ggrid, 256>>>(queries, Wq, bq, gq, Mrows, DMODEL, DMODEL);
    sgemm_bias<<<ggrid, 256>>>(keys,    Wk, bk, gk, Mrows, DMODEL, DMODEL);
    sgemm_bias<<<ggrid, 256>>>(values,  Wv, bv, gv, Mrows, DMODEL, DMODEL);

    // 4: global key max per (b,h)
    kmax_kernel<<<BB * HH, 256>>>(gk, gkm);

    // 5-6: FAVOR feature maps (in place)
    favor_kernel<<<NROWS / 64, 512>>>(gq, Wfq, gkm, 1);
    favor_kernel<<<NROWS / 64, 512>>>(gk, Wfk, gkm, 0);

    // 7: causal scan
    scan_kernel<<<BB * HH, 256>>>(gq, gk, gv, go);

    // 8: output projection
    sgemm_bias<<<ggrid, 256>>>(go, Wo, bo, out, Mrows, DMODEL, DMODEL);
}

// round 2
// speedup vs baseline: 1.8440x; 1.8440x over previous
#include <cuda_runtime.h>
#include <math.h>

// Problem constants (fixed by the dataset)
#define BB   2
#define LL   4096
#define HH   16
#define MM   64
#define DMODEL 1024
#define NROWS (BB*LL*HH)          // 131072 (b,l,h) rows of 64 features
#define DN    0.3535533905932738f // 64^{-1/4}
#define DIAGC 0.0625f             // 0.5*dn*dn
#define INVSQRTM 0.125f           // 1/sqrt(64)

#define CT   64                   // chunk length (tokens)
#define NC   (LL/CT)              // 64 chunks
#define NBH  (BB*HH)              // 32

// Scratch (static device arrays; no allocation allowed)
__device__ float g_q[BB*LL*DMODEL];
__device__ float g_k[BB*LL*DMODEL];
__device__ float g_v[BB*LL*DMODEL];
__device__ float g_o[BB*LL*DMODEL];
__device__ float g_kmax[NBH];
__device__ float g_kpart[NBH*16];
__device__ float g_kv[NBH*NC*MM*MM];   // per-chunk KV sums -> exclusive prefix
__device__ float g_ks[NBH*NC*MM];      // per-chunk k sums  -> exclusive prefix

// ---------------------------------------------------------------------------
// SGEMM (double buffered): C[M,N] = A[M,K] @ W[K,N] + bias[N]  (row-major fp32)
// 128x128 tile, BK=16, 256 threads, 8x8 per thread, register prefetch.
// ---------------------------------------------------------------------------
#define GBM 128
#define GBN 128
#define GBK 16

__global__ __launch_bounds__(256, 2)
void sgemm_bias(const float* __restrict__ A, const float* __restrict__ W,
                const float* __restrict__ bias, float* __restrict__ C,
                int M, int N, int K)
{
    __shared__ float As[2][GBK][GBM];
    __shared__ float Ws[2][GBK][GBN];

    const int tid = threadIdx.x;
    const int bm = blockIdx.y * GBM;
    const int bn = blockIdx.x * GBN;

    // A tile: 128 rows x 16 cols. Each thread: 2 float4 (cols c0..c0+3, c0+8..c0+11)
    const int a_row = tid >> 1;
    const int a_c0  = (tid & 1) * 4;
    // W tile: 16 rows x 128 cols. Each thread: 2 float4 (8 contiguous cols)
    const int w_row = tid >> 4;          // 0..15
    const int w_col = (tid & 15) * 8;

    const int tx = tid & 15;
    const int ty = tid >> 4;

    const float* Ap = A + (size_t)(bm + a_row) * K + a_c0;
    const float* Wp = W + (size_t)w_row * N + bn + w_col;

    float acc[8][8];
#pragma unroll
    for (int i = 0; i < 8; i++)
#pragma unroll
        for (int j = 0; j < 8; j++) acc[i][j] = 0.f;

    // preload tile 0
    float4 a0 = *(const float4*)(Ap);
    float4 a1 = *(const float4*)(Ap + 8);
    float4 w0 = *(const float4*)(Wp);
    float4 w1 = *(const float4*)(Wp + 4);

    As[0][a_c0 + 0][a_row] = a0.x; As[0][a_c0 + 1][a_row] = a0.y;
    As[0][a_c0 + 2][a_row] = a0.z; As[0][a_c0 + 3][a_row] = a0.w;
    As[0][a_c0 + 8][a_row] = a1.x; As[0][a_c0 + 9][a_row] = a1.y;
    As[0][a_c0 +10][a_row] = a1.z; As[0][a_c0 +11][a_row] = a1.w;
    *(float4*)&Ws[0][w_row][w_col]     = w0;
    *(float4*)&Ws[0][w_row][w_col + 4] = w1;
    __syncthreads();

    const int iters = K / GBK;
    int buf = 0;
    for (int k0 = 0; k0 < iters; k0++) {
        if (k0 + 1 < iters) {
            a0 = *(const float4*)(Ap + (k0 + 1) * GBK);
            a1 = *(const float4*)(Ap + (k0 + 1) * GBK + 8);
            w0 = *(const float4*)(Wp + (size_t)(k0 + 1) * GBK * N);
            w1 = *(const float4*)(Wp + (size_t)(k0 + 1) * GBK * N + 4);
        }
#pragma unroll
        for (int k = 0; k < GBK; k++) {
            float af[8], wf[8];
            *(float4*)&af[0] = *(const float4*)&As[buf][k][ty * 8];
            *(float4*)&af[4] = *(const float4*)&As[buf][k][ty * 8 + 4];
            *(float4*)&wf[0] = *(const float4*)&Ws[buf][k][tx * 8];
            *(float4*)&wf[4] = *(const float4*)&Ws[buf][k][tx * 8 + 4];
#pragma unroll
            for (int i = 0; i < 8; i++)
#pragma unroll
                for (int j = 0; j < 8; j++)
                    acc[i][j] = fmaf(af[i], wf[j], acc[i][j]);
        }
        if (k0 + 1 < iters) {
            int nb = buf ^ 1;
            As[nb][a_c0 + 0][a_row] = a0.x; As[nb][a_c0 + 1][a_row] = a0.y;
            As[nb][a_c0 + 2][a_row] = a0.z; As[nb][a_c0 + 3][a_row] = a0.w;
            As[nb][a_c0 + 8][a_row] = a1.x; As[nb][a_c0 + 9][a_row] = a1.y;
            As[nb][a_c0 +10][a_row] = a1.z; As[nb][a_c0 +11][a_row] = a1.w;
            *(float4*)&Ws[nb][w_row][w_col]     = w0;
            *(float4*)&Ws[nb][w_row][w_col + 4] = w1;
        }
        __syncthreads();
        buf ^= 1;
    }

    float bvals[8];
#pragma unroll
    for (int j = 0; j < 8; j++) bvals[j] = bias[bn + tx * 8 + j];

#pragma unroll
    for (int i = 0; i < 8; i++) {
        float* crow = C + (size_t)(bm + ty * 8 + i) * N + bn + tx * 8;
        float4 o0, o1;
        o0.x = acc[i][0] + bvals[0]; o0.y = acc[i][1] + bvals[1];
        o0.z = acc[i][2] + bvals[2]; o0.w = acc[i][3] + bvals[3];
        o1.x = acc[i][4] + bvals[4]; o1.y = acc[i][5] + bvals[5];
        o1.z = acc[i][6] + bvals[6]; o1.w = acc[i][7] + bvals[7];
        *(float4*)(crow)     = o0;
        *(float4*)(crow + 4) = o1;
    }
}

// ---------------------------------------------------------------------------
// kmax stage 1: per (b,h,slice) partial max over 256 l-rows
// ---------------------------------------------------------------------------
__global__ void kmax_part_kernel(const float* __restrict__ Kp, float* __restrict__ kpart)
{
    const int bh = blockIdx.y;             // 0..31
    const int sl = blockIdx.x;             // 0..15
    const int b = bh >> 4, h = bh & 15;
    const int tid = threadIdx.x;           // 256
    float m = -1e30f;
    const int l0 = sl * 256;
    for (int idx = tid; idx < 256 * MM; idx += 256) {
        int l = l0 + (idx >> 6), mm = idx & 63;
        float v = Kp[((size_t)(b * LL + l) * HH + h) * MM + mm];
        m = fmaxf(m, v);
    }
    __shared__ float red[256];
    red[tid] = m;
    __syncthreads();
    for (int s = 128; s > 0; s >>= 1) {
        if (tid < s) red[tid] = fmaxf(red[tid], red[tid + s]);
        __syncthreads();
    }
    if (tid == 0) kpart[bh * 16 + sl] = red[0];
}

__global__ void kmax_final_kernel(const float* __restrict__ kpart, float* __restrict__ kmax)
{
    const int bh = blockIdx.x;
    const int t = threadIdx.x;   // 16
    __shared__ float red[16];
    red[t] = kpart[bh * 16 + t];
    __syncthreads();
    if (t < 8) red[t] = fmaxf(red[t], red[t + 8]);
    __syncthreads();
    if (t < 4) red[t] = fmaxf(red[t], red[t + 4]);
    __syncthreads();
    if (t == 0) kmax[bh] = DN * fmaxf(fmaxf(red[0], red[1]), fmaxf(red[2], red[3]));
}

// ---------------------------------------------------------------------------
// FAVOR feature map (in-place)
// ---------------------------------------------------------------------------
__global__ __launch_bounds__(512)
void favor_kernel(float* __restrict__ X, const float* __restrict__ Wf,
                  const float* __restrict__ kmax, int is_query)
{
    __shared__ float Wt[64][65];
    __shared__ float xs[8][64];

    const int tid = threadIdx.x;
    for (int i = tid; i < 64 * 64; i += 512) {
        int d = i >> 6, m = i & 63;
        Wt[m][d] = Wf[i];
    }
    __syncthreads();

    const int r = tid >> 6;
    const int d = tid & 63;

    for (int pass = 0; pass < 8; pass++) {
        int row = blockIdx.x * 64 + pass * 8 + r;
        xs[r][d] = DN * X[(size_t)row * 64 + d];
        __syncthreads();

        float dot = 0.f, ss = 0.f, mx = -1e30f;
#pragma unroll 8
        for (int m = 0; m < 64; m++) {
            float x = xs[r][m];
            dot = fmaf(Wt[m][d], x, dot);
            ss  = fmaf(x, x, ss);
            mx  = fmaxf(mx, x);
        }
        float mq;
        if (is_query) {
            mq = mx;
        } else {
            int h = row & 15;
            int b = row >> 16;
            mq = kmax[b * HH + h];
        }
        float phi = INVSQRTM * __expf(dot - DIAGC * ss - mq + 1e-8f);
        __syncthreads();
        X[(size_t)row * 64 + d] = phi;
    }
}

// ---------------------------------------------------------------------------
// chunk_sum: per (bh, chunk) compute KV[64][64] = sum_l k_l (x) v_l and ksum[64]
// grid (NC, NBH), 256 threads
// ---------------------------------------------------------------------------
__global__ __launch_bounds__(256)
void chunk_sum_kernel(const float* __restrict__ Kp, const float* __restrict__ V,
                      float* __restrict__ kv, float* __restrict__ ks)
{
    __shared__ __align__(16) float kss[CT][64];
    __shared__ __align__(16) float vss[CT][64];

    const int c  = blockIdx.x;
    const int bh = blockIdx.y;
    const int b = bh >> 4, h = bh & 15;
    const int tid = threadIdx.x;
    const size_t base = ((size_t)(b * LL + c * CT) * HH + h) * MM;
    const size_t stride = HH * MM;   // 1024

    for (int i = tid; i < CT * 16; i += 256) {
        int l = i >> 4, m4 = (i & 15) * 4;
        *(float4*)&kss[l][m4] = *(const float4*)&Kp[base + (size_t)l * stride + m4];
        *(float4*)&vss[l][m4] = *(const float4*)&V[base + (size_t)l * stride + m4];
    }
    __syncthreads();

    const int g = tid >> 6;   // m group
    const int d = tid & 63;

    float S[16];
#pragma unroll
    for (int j = 0; j < 16; j++) S[j] = 0.f;

    for (int l = 0; l < CT; l++) {
        float vd = vss[l][d];
        float kf[16];
#pragma unroll
        for (int jj = 0; jj < 4; jj++)
            *(float4*)&kf[jj * 4] = *(const float4*)&kss[l][g * 16 + jj * 4];
#pragma unroll
        for (int j = 0; j < 16; j++) S[j] = fmaf(kf[j], vd, S[j]);
    }

    float* out = kv + ((size_t)(bh * NC + c) * MM) * MM;
#pragma unroll
    for (int j = 0; j < 16; j++)
        out[(size_t)(g * 16 + j) * 64 + d] = S[j];

    if (tid < 64) {
        float s = 0.f;
        for (int l = 0; l < CT; l++) s += kss[l][tid];
        ks[(size_t)(bh * NC + c) * MM + tid] = s;
    }
}

// ---------------------------------------------------------------------------
// prefix: exclusive prefix over chunks, in place.
// grid (4, NBH): block handles 16 d-cols. 256 threads x 4 cells (float4).
// ---------------------------------------------------------------------------
__global__ __launch_bounds__(256)
void prefix_kernel(float* __restrict__ kv, float* __restrict__ ks)
{
    const int dg = blockIdx.x;    // 0..3
    const int bh = blockIdx.y;
    const int tid = threadIdx.x;
    const int m = tid >> 2;
    const int d = dg * 16 + (tid & 3) * 4;

    float4 run = make_float4(0.f, 0.f, 0.f, 0.f);
    for (int c = 0; c < NC; c++) {
        float* p = kv + ((size_t)(bh * NC + c) * MM + m) * MM + d;
        float4 val = *(float4*)p;
        *(float4*)p = run;
        run.x += val.x; run.y += val.y; run.z += val.z; run.w += val.w;
    }

    if (dg == 0 && tid < 64) {
        float r = 0.f;
        for (int c = 0; c < NC; c++) {
            float* p = ks + (size_t)(bh * NC + c) * MM + tid;
            float v = *p;
            *p = r;
            r += v;
        }
    }
}

// ---------------------------------------------------------------------------
// chunk_attn: per (bh, chunk):
//   A = tril(Q K^T); num = A V + Q S_pre; den = rowsum(A) + Q z_pre; out = num/den
// grid (NC, NBH), 256 threads, dynamic smem.
// ---------------------------------------------------------------------------
#define PAD 68
__global__ __launch_bounds__(256)
void chunk_attn_kernel(const float* __restrict__ Q, const float* __restrict__ Kp,
                       const float* __restrict__ V, const float* __restrict__ kv,
                       const float* __restrict__ ksum, float* __restrict__ Out)
{
    extern __shared__ float sm[];
    float* Qt   = sm;                     // [64][PAD]  Qt[m][r] = Q[r][m]
    float* Kt   = Qt + 64 * PAD;          // [64][PAD]  Kt[m][c] = K[c][m]
    float* Vs   = Kt + 64 * PAD;          // [64][PAD]  Vs[c][d]
    float* Sp   = Vs + 64 * PAD;          // [64][PAD]  Sp[m][d]
    float* At   = Sp + 64 * PAD;          // [64][PAD]  At[c][r] = A[r][c]
    float* zpre = At + 64 * PAD;          // [64]
    float* den  = zpre + 64;              // [64]

    const int c  = blockIdx.x;
    const int bh = blockIdx.y;
    const int b = bh >> 4, h = bh & 15;
    const int tid = threadIdx.x;
    const size_t base = ((size_t)(b * LL + c * CT) * HH + h) * MM;
    const size_t stride = HH * MM;

    // loads
    for (int i = tid; i < 64 * 16; i += 256) {
        int r = i >> 4, m4 = (i & 15) * 4;
        float4 q = *(const float4*)&Q[base + (size_t)r * stride + m4];
        Qt[(m4 + 0) * PAD + r] = q.x; Qt[(m4 + 1) * PAD + r] = q.y;
        Qt[(m4 + 2) * PAD + r] = q.z; Qt[(m4 + 3) * PAD + r] = q.w;
        float4 k = *(const float4*)&Kp[base + (size_t)r * stride + m4];
        Kt[(m4 + 0) * PAD + r] = k.x; Kt[(m4 + 1) * PAD + r] = k.y;
        Kt[(m4 + 2) * PAD + r] = k.z; Kt[(m4 + 3) * PAD + r] = k.w;
        *(float4*)&Vs[r * PAD + m4] = *(const float4*)&V[base + (size_t)r * stride + m4];
        *(float4*)&Sp[r * PAD + m4] =
            *(const float4*)&kv[((size_t)(bh * NC + c) * MM + r) * MM + m4];
    }
    if (tid < 64) zpre[tid] = ksum[(size_t)(bh * NC + c) * MM + tid];
    __syncthreads();

    const int ty = tid >> 4;       // row group: rows ty*4..ty*4+3
    const int tx = tid & 15;       // col group: cols tx*4..tx*4+3
    const int r0 = ty * 4, c0 = tx * 4;

    // Phase 1: A = Q K^T
    float a[4][4];
#pragma unroll
    for (int i = 0; i < 4; i++)
#pragma unroll
        for (int j = 0; j < 4; j++) a[i][j] = 0.f;

    for (int m = 0; m < 64; m++) {
        float4 qv = *(float4*)&Qt[m * PAD + r0];
        float4 kv4 = *(float4*)&Kt[m * PAD + c0];
        float qf[4] = {qv.x, qv.y, qv.z, qv.w};
        float kf[4] = {kv4.x, kv4.y, kv4.z, kv4.w};
#pragma unroll
        for (int i = 0; i < 4; i++)
#pragma unroll
            for (int j = 0; j < 4; j++)
                a[i][j] = fmaf(qf[i], kf[j], a[i][j]);
    }
    // masked store (At[c][r])
#pragma unroll
    for (int j = 0; j < 4; j++)
#pragma unroll
        for (int i = 0; i < 4; i++)
            At[(c0 + j) * PAD + (r0 + i)] = (c0 + j <= r0 + i) ? a[i][j] : 0.f;
    __syncthreads();

    // den[r] = rowsum(A) + q_r . zpre
    if (tid < 64) {
        int r = tid;
        float s = 0.f;
        for (int cc = 0; cc < 64; cc++) s += At[cc * PAD + r];
        for (int m = 0; m < 64; m++) s = fmaf(Qt[m * PAD + r], zpre[m], s);
        den[r] = s;
    }

    // Phase 2: num = A V + Q S_pre
    float o[4][4];
#pragma unroll
    for (int i = 0; i < 4; i++)
#pragma unroll
        for (int j = 0; j < 4; j++) o[i][j] = 0.f;

    for (int cc = 0; cc < 64; cc++) {
        float4 av = *(float4*)&At[cc * PAD + r0];
        float4 vv = *(float4*)&Vs[cc * PAD + c0];
        float af[4] = {av.x, av.y, av.z, av.w};
        float vf[4] = {vv.x, vv.y, vv.z, vv.w};
#pragma unroll
        for (int i = 0; i < 4; i++)
#pragma unroll
            for (int j = 0; j < 4; j++)
                o[i][j] = fmaf(af[i], vf[j], o[i][j]);
    }
    for (int m = 0; m < 64; m++) {
        float4 qv = *(float4*)&Qt[m * PAD + r0];
        float4 sv = *(float4*)&Sp[m * PAD + c0];
        float qf[4] = {qv.x, qv.y, qv.z, qv.w};
        float sf[4] = {sv.x, sv.y, sv.z, sv.w};
#pragma unroll
        for (int i = 0; i < 4; i++)
#pragma unroll
            for (int j = 0; j < 4; j++)
                o[i][j] = fmaf(qf[i], sf[j], o[i][j]);
    }
    __syncthreads();

#pragma unroll
    for (int i = 0; i < 4; i++) {
        float dinv = 1.f / den[r0 + i];
        float4 w;
        w.x = o[i][0] * dinv; w.y = o[i][1] * dinv;
        w.z = o[i][2] * dinv; w.w = o[i][3] * dinv;
        *(float4*)&Out[base + (size_t)(r0 + i) * stride + c0] = w;
    }
}

// ---------------------------------------------------------------------------
// Launch
// ---------------------------------------------------------------------------
extern "C" void kernel_launch(void* const* d_in, const int* in_sizes, int n_in,
                              void* d_out, int out_size)
{
    const float* queries = (const float*)d_in[0];
    const float* keys    = (const float*)d_in[1];
    const float* values  = (const float*)d_in[2];
    const float* Wq = (const float*)d_in[3];
    const float* bq = (const float*)d_in[4];
    const float* Wk = (const float*)d_in[5];
    const float* bk = (const float*)d_in[6];
    const float* Wv = (const float*)d_in[7];
    const float* bv = (const float*)d_in[8];
    const float* Wo = (const float*)d_in[9];
    const float* bo = (const float*)d_in[10];
    const float* Wfq = (const float*)d_in[11];
    const float* Wfk = (const float*)d_in[12];
    float* out = (float*)d_out;

    float *gq, *gk, *gv, *go, *gkm, *gkp, *gkv, *gks;
    cudaGetSymbolAddress((void**)&gq, g_q);
    cudaGetSymbolAddress((void**)&gk, g_k);
    cudaGetSymbolAddress((void**)&gv, g_v);
    cudaGetSymbolAddress((void**)&go, g_o);
    cudaGetSymbolAddress((void**)&gkm, g_kmax);
    cudaGetSymbolAddress((void**)&gkp, g_kpart);
    cudaGetSymbolAddress((void**)&gkv, g_kv);
    cudaGetSymbolAddress((void**)&gks, g_ks);

    const int Mrows = BB * LL;                 // 8192
    dim3 ggrid(DMODEL / GBN, Mrows / GBM);     // (8, 64)

    // projections
    sgemm_bias<<<ggrid, 256>>>(queries, Wq, bq, gq, Mrows, DMODEL, DMODEL);
    sgemm_bias<<<ggrid, 256>>>(keys,    Wk, bk, gk, Mrows, DMODEL, DMODEL);
    sgemm_bias<<<ggrid, 256>>>(values,  Wv, bv, gv, Mrows, DMODEL, DMODEL);

    // key global max
    kmax_part_kernel<<<dim3(16, NBH), 256>>>(gk, gkp);
    kmax_final_kernel<<<NBH, 16>>>(gkp, gkm);

    // FAVOR feature maps (in place)
    favor_kernel<<<NROWS / 64, 512>>>(gq, Wfq, gkm, 1);
    favor_kernel<<<NROWS / 64, 512>>>(gk, Wfk, gkm, 0);

    // chunked causal linear attention
    chunk_sum_kernel<<<dim3(NC, NBH), 256>>>(gk, gv, gkv, gks);
    prefix_kernel<<<dim3(4, NBH), 256>>>(gkv, gks);

    static const int attn_smem = (5 * 64 * PAD + 128) * sizeof(float);
    cudaFuncSetAttribute(chunk_attn_kernel,
                         cudaFuncAttributeMaxDynamicSharedMemorySize, attn_smem);
    chunk_attn_kernel<<<dim3(NC, NBH), 256, attn_smem>>>(gq, gk, gv, gkv, gks, go);

    // output projection
    sgemm_bias<<<ggrid, 256>>>(go, Wo, bo, out, Mrows, DMODEL, DMODEL);
}

// round 4
// speedup vs baseline: 4.1128x; 2.2303x over previous
#include <cuda_runtime.h>
#include <cuda_bf16.h>
#include <math.h>
#include <stdint.h>

// Problem constants (fixed by the dataset)
#define BB   2
#define LL   4096
#define HH   16
#define MM   64
#define DMODEL 1024
#define NROWS (BB*LL*HH)
#define DN    0.3535533905932738f
#define DIAGC 0.0625f
#define INVSQRTM 0.125f

#define CT   64
#define NC   (LL/CT)
#define NBH  (BB*HH)
#define MROWS (BB*LL)             // 8192

// ---------------------------------------------------------------------------
// scratch
// ---------------------------------------------------------------------------
__device__ float g_q[MROWS*DMODEL];
__device__ float g_k[MROWS*DMODEL];
__device__ float g_v[MROWS*DMODEL];
__device__ float g_kmax[NBH];
__device__ float g_kpart[NBH*16];
__device__ float g_kv[NBH*NC*MM*MM];
__device__ float g_ks[NBH*NC*MM];
__device__ __align__(16) __nv_bfloat16 g_xh[3*MROWS*DMODEL];
__device__ __align__(16) __nv_bfloat16 g_xl[3*MROWS*DMODEL];
__device__ __align__(16) __nv_bfloat16 g_oh[MROWS*DMODEL];
__device__ __align__(16) __nv_bfloat16 g_ol[MROWS*DMODEL];
__device__ __align__(16) __nv_bfloat16 g_wh[4*DMODEL*DMODEL];
__device__ __align__(16) __nv_bfloat16 g_wl[4*DMODEL*DMODEL];

// ---------------------------------------------------------------------------
// helpers (portable: compute_80+ features only; NO tcgen05)
// ---------------------------------------------------------------------------
__device__ __forceinline__ uint32_t smem_to_u32(const void* p) {
    uint32_t a;
    asm("{ .reg .u64 t; cvta.to.shared.u64 t, %1; cvt.u32.u64 %0, t; }"
        : "=r"(a) : "l"(p));
    return a;
}
#define SWZ128(b) ((b) ^ (((b) >> 3) & 0x70))

__device__ __forceinline__ void cp16(uint32_t dst, const void* src) {
    asm volatile("cp.async.cg.shared.global [%0], [%1], 16;" :: "r"(dst), "l"(src));
}
__device__ __forceinline__ void cp_commit() {
    asm volatile("cp.async.commit_group;" ::: "memory");
}
template<int N> __device__ __forceinline__ void cp_wait() {
    asm volatile("cp.async.wait_group %0;" :: "n"(N) : "memory");
}
__device__ __forceinline__ void ldsm4(uint32_t (&r)[4], uint32_t addr) {
    asm volatile("ldmatrix.sync.aligned.m8n8.x4.shared.b16 {%0,%1,%2,%3}, [%4];"
        : "=r"(r[0]), "=r"(r[1]), "=r"(r[2]), "=r"(r[3]) : "r"(addr));
}
__device__ __forceinline__ void mma16816(float (&d)[4], const uint32_t (&a)[4],
                                         const uint32_t* b) {
    asm volatile("mma.sync.aligned.m16n8k16.row.col.f32.bf16.bf16.f32 "
        "{%0,%1,%2,%3}, {%4,%5,%6,%7}, {%8,%9}, {%0,%1,%2,%3};"
        : "+f"(d[0]), "+f"(d[1]), "+f"(d[2]), "+f"(d[3])
        : "r"(a[0]), "r"(a[1]), "r"(a[2]), "r"(a[3]), "r"(b[0]), "r"(b[1]));
}

// ---------------------------------------------------------------------------
// bf16x3 HMMA GEMM: C[8192,1024] = (Ah+Al)[8192,1024] @ (Bh+Bl)^T + bias
//   A*: [Mrows,1024] bf16 row-major; B*: [1024 n][1024 k] bf16 (pre-transposed W)
//   CTA tile 128x128, K-chunk 64, cp.async 2-stage double buffer.
//   C = Ah*Bh + Ah*Bl + Al*Bh (fp32 accum).
// ---------------------------------------------------------------------------
#define GM_TILE  16384                  // 128 rows x 64 bf16 = 16KB
#define GM_STAGE (4*GM_TILE)            // Ah,Al,Bh,Bl
#define GM_SMEM  (2*GM_STAGE)           // 128KB
#define GM_NKC   16

__device__ __forceinline__ void gm_cp_chunk(
    uint32_t stage,
    const __nv_bfloat16* Ah, const __nv_bfloat16* Al,
    const __nv_bfloat16* Bh, const __nv_bfloat16* Bl,
    int bm, int bn, int kc, int r_lo, int cb)
{
    const size_t ko = (size_t)kc * 128 + cb;
#pragma unroll
    for (int j = 0; j < 4; j++) {
        const int row = r_lo + 32 * j;
        const uint32_t swz = SWZ128((uint32_t)(row * 128 + cb));
        cp16(stage + 0 * GM_TILE + swz, (const char*)Ah + (size_t)(bm + row) * 2048 + ko);
        cp16(stage + 1 * GM_TILE + swz, (const char*)Al + (size_t)(bm + row) * 2048 + ko);
        cp16(stage + 2 * GM_TILE + swz, (const char*)Bh + (size_t)(bn + row) * 2048 + ko);
        cp16(stage + 3 * GM_TILE + swz, (const char*)Bl + (size_t)(bn + row) * 2048 + ko);
    }
    cp_commit();
}

__device__ __forceinline__ void gm_compute(uint32_t st, int wm, int wn, int lid,
                                           float acc[2][8][4])
{
    const int ar  = wm + (lid & 15);
    const int akb = (lid >> 4) * 16;
    const int br  = (lid & 7) + ((lid >> 4) << 3);
    const int bkb = ((lid >> 3) & 1) * 16;
#pragma unroll
    for (int k0 = 0; k0 < 4; k0++) {
        const int kb = k0 * 32;
        const uint32_t a0off = SWZ128((uint32_t)(ar * 128 + kb + akb));
        const uint32_t a1off = SWZ128((uint32_t)((ar + 16) * 128 + kb + akb));
        uint32_t ah[2][4], al[2][4];
        ldsm4(ah[0], st + a0off);
        ldsm4(ah[1], st + a1off);
        ldsm4(al[0], st + GM_TILE + a0off);
        ldsm4(al[1], st + GM_TILE + a1off);
        uint32_t bh[4][4], bl[4][4];
#pragma unroll
        for (int g = 0; g < 4; g++) {
            const uint32_t boff = SWZ128((uint32_t)((wn + g * 16 + br) * 128 + kb + bkb));
            ldsm4(bh[g], st + 2 * GM_TILE + boff);
            ldsm4(bl[g], st + 3 * GM_TILE + boff);
        }
#pragma unroll
        for (int mt = 0; mt < 2; mt++) {
#pragma unroll
            for (int g = 0; g < 4; g++) {
                mma16816(acc[mt][2 * g],     ah[mt], &bh[g][0]);
                mma16816(acc[mt][2 * g + 1], ah[mt], &bh[g][2]);
                mma16816(acc[mt][2 * g],     ah[mt], &bl[g][0]);
                mma16816(acc[mt][2 * g + 1], ah[mt], &bl[g][2]);
                mma16816(acc[mt][2 * g],     al[mt], &bh[g][0]);
                mma16816(acc[mt][2 * g + 1], al[mt], &bh[g][2]);
            }
        }
    }
}

__global__ __launch_bounds__(256, 1)
void gemm_bf16x3(const __nv_bfloat16* __restrict__ Ah, const __nv_bfloat16* __restrict__ Al,
                 const __nv_bfloat16* __restrict__ Bh, const __nv_bfloat16* __restrict__ Bl,
                 const float* __restrict__ bias, float* __restrict__ C)
{
    extern __shared__ char smem[];
    const uint32_t sb = smem_to_u32(smem);
    const int tid = threadIdx.x;
    const int wid = tid >> 5, lid = tid & 31;
    const int bn = blockIdx.x * 128;
    const int bm = blockIdx.y * 128;
    const int r_lo = tid >> 3;
    const int cb = (tid & 7) * 16;
    const int wm = (wid & 3) * 32;
    const int wn = (wid >> 2) * 64;

    float acc[2][8][4];
#pragma unroll
    for (int mt = 0; mt < 2; mt++)
#pragma unroll
        for (int nt = 0; nt < 8; nt++)
#pragma unroll
            for (int j = 0; j < 4; j++) acc[mt][nt][j] = 0.f;

    gm_cp_chunk(sb,            Ah, Al, Bh, Bl, bm, bn, 0, r_lo, cb);
    gm_cp_chunk(sb + GM_STAGE, Ah, Al, Bh, Bl, bm, bn, 1, r_lo, cb);

    for (int i = 0; i < GM_NKC; i++) {
        if (i < GM_NKC - 2) cp_wait<1>(); else cp_wait<0>();
        __syncthreads();
        gm_compute(sb + (uint32_t)(i & 1) * GM_STAGE, wm, wn, lid, acc);
        __syncthreads();
        if (i + 2 < GM_NKC)
            gm_cp_chunk(sb + (uint32_t)(i & 1) * GM_STAGE,
                        Ah, Al, Bh, Bl, bm, bn, i + 2, r_lo, cb);
    }

    // epilogue: bias + write fp32
    const int row_b = bm + wm + (lid >> 2);
    const int col_b = bn + wn + (lid & 3) * 2;
#pragma unroll
    for (int mt = 0; mt < 2; mt++) {
#pragma unroll
        for (int nt = 0; nt < 8; nt++) {
            const int col = col_b + nt * 8;
            const float b0 = bias[col], b1 = bias[col + 1];
            const int r0 = row_b + mt * 16;
            float2 v0, v1;
            v0.x = acc[mt][nt][0] + b0; v0.y = acc[mt][nt][1] + b1;
            v1.x = acc[mt][nt][2] + b0; v1.y = acc[mt][nt][3] + b1;
            *(float2*)&C[(size_t)r0 * DMODEL + col] = v0;
            *(float2*)&C[(size_t)(r0 + 8) * DMODEL + col] = v1;
        }
    }
}

// ---------------------------------------------------------------------------
// fp32 -> bf16 hi/lo split
// ---------------------------------------------------------------------------
__global__ __launch_bounds__(256)
void cvt_hl_kernel(const float* __restrict__ x, __nv_bfloat16* __restrict__ h,
                   __nv_bfloat16* __restrict__ l)
{
    const int i = (blockIdx.x * 256 + threadIdx.x) * 4;
    float4 v = *(const float4*)(x + i);
    __nv_bfloat16 h0 = __float2bfloat16(v.x), h1 = __float2bfloat16(v.y);
    __nv_bfloat16 h2 = __float2bfloat16(v.z), h3 = __float2bfloat16(v.w);
    __nv_bfloat16 l0 = __float2bfloat16(v.x - __bfloat162float(h0));
    __nv_bfloat16 l1 = __float2bfloat16(v.y - __bfloat162float(h1));
    __nv_bfloat16 l2 = __float2bfloat16(v.z - __bfloat162float(h2));
    __nv_bfloat16 l3 = __float2bfloat16(v.w - __bfloat162float(h3));
    __nv_bfloat162* ph = (__nv_bfloat162*)(h + i);
    ph[0] = __halves2bfloat162(h0, h1); ph[1] = __halves2bfloat162(h2, h3);
    __nv_bfloat162* pl = (__nv_bfloat162*)(l + i);
    pl[0] = __halves2bfloat162(l0, l1); pl[1] = __halves2bfloat162(l2, l3);
}

// ---------------------------------------------------------------------------
// weight transpose + hi/lo split: Th[n][k] = bf16hi(W[k][n])
// ---------------------------------------------------------------------------
__global__ __launch_bounds__(256)
void wt_cvt_kernel(const float* __restrict__ W, __nv_bfloat16* __restrict__ Th,
                   __nv_bfloat16* __restrict__ Tl)
{
    __shared__ float t[32][33];
    const int kx = blockIdx.x * 32;
    const int nx = blockIdx.y * 32;
    const int tx = threadIdx.x & 31, ty = threadIdx.x >> 5;
    for (int r = ty; r < 32; r += 8)
        t[r][tx] = W[(size_t)(kx + r) * DMODEL + nx + tx];
    __syncthreads();
    for (int r = ty; r < 32; r += 8) {
        float v = t[tx][r];
        __nv_bfloat16 h = __float2bfloat16(v);
        __nv_bfloat16 lo = __float2bfloat16(v - __bfloat162float(h));
        Th[(size_t)(nx + r) * DMODEL + kx + tx] = h;
        Tl[(size_t)(nx + r) * DMODEL + kx + tx] = lo;
    }
}

// ---------------------------------------------------------------------------
// kmax (two stage)
// ---------------------------------------------------------------------------
__global__ void kmax_part_kernel(const float* __restrict__ Kp, float* __restrict__ kpart)
{
    const int bh = blockIdx.y, sl = blockIdx.x;
    const int b = bh >> 4, h = bh & 15;
    const int tid = threadIdx.x;
    float m = -1e30f;
    const int l0 = sl * 256;
    for (int idx = tid; idx < 256 * MM; idx += 256) {
        int l = l0 + (idx >> 6), mm = idx & 63;
        m = fmaxf(m, Kp[((size_t)(b * LL + l) * HH + h) * MM + mm]);
    }
    __shared__ float red[256];
    red[tid] = m;
    __syncthreads();
    for (int s = 128; s > 0; s >>= 1) {
        if (tid < s) red[tid] = fmaxf(red[tid], red[tid + s]);
        __syncthreads();
    }
    if (tid == 0) kpart[bh * 16 + sl] = red[0];
}

__global__ void kmax_final_kernel(const float* __restrict__ kpart, float* __restrict__ kmax)
{
    const int bh = blockIdx.x;
    const int t = threadIdx.x;
    __shared__ float red[16];
    red[t] = kpart[bh * 16 + t];
    __syncthreads();
    if (t < 8) red[t] = fmaxf(red[t], red[t + 8]);
    __syncthreads();
    if (t < 4) red[t] = fmaxf(red[t], red[t + 4]);
    __syncthreads();
    if (t == 0) kmax[bh] = DN * fmaxf(fmaxf(red[0], red[1]), fmaxf(red[2], red[3]));
}

// ---------------------------------------------------------------------------
// FAVOR feature map (in-place)
// ---------------------------------------------------------------------------
__global__ __launch_bounds__(512)
void favor_kernel(float* __restrict__ X, const float* __restrict__ Wf,
                  const float* __restrict__ kmax, int is_query)
{
    __shared__ float Wt[64][65];
    __shared__ float xs[8][64];
    const int tid = threadIdx.x;
    for (int i = tid; i < 64 * 64; i += 512) {
        int d = i >> 6, m = i & 63;
        Wt[m][d] = Wf[i];
    }
    __syncthreads();
    const int r = tid >> 6;
    const int d = tid & 63;
    for (int pass = 0; pass < 8; pass++) {
        int row = blockIdx.x * 64 + pass * 8 + r;
        xs[r][d] = DN * X[(size_t)row * 64 + d];
        __syncthreads();
        float dot = 0.f, ss = 0.f, mx = -1e30f;
#pragma unroll 8
        for (int m = 0; m < 64; m++) {
            float x = xs[r][m];
            dot = fmaf(Wt[m][d], x, dot);
            ss  = fmaf(x, x, ss);
            mx  = fmaxf(mx, x);
        }
        float mq;
        if (is_query) mq = mx;
        else {
            int h = row & 15;
            int b = row >> 16;
            mq = kmax[b * HH + h];
        }
        float phi = INVSQRTM * __expf(dot - DIAGC * ss - mq + 1e-8f);
        __syncthreads();
        X[(size_t)row * 64 + d] = phi;
    }
}

// ---------------------------------------------------------------------------
// chunk_sum
// ---------------------------------------------------------------------------
__global__ __launch_bounds__(256)
void chunk_sum_kernel(const float* __restrict__ Kp, const float* __restrict__ V,
                      float* __restrict__ kv, float* __restrict__ ks)
{
    __shared__ __align__(16) float kss[CT][64];
    __shared__ __align__(16) float vss[CT][64];
    const int c  = blockIdx.x;
    const int bh = blockIdx.y;
    const int b = bh >> 4, h = bh & 15;
    const int tid = threadIdx.x;
    const size_t base = ((size_t)(b * LL + c * CT) * HH + h) * MM;
    const size_t stride = HH * MM;

    for (int i = tid; i < CT * 16; i += 256) {
        int l = i >> 4, m4 = (i & 15) * 4;
        *(float4*)&kss[l][m4] = *(const float4*)&Kp[base + (size_t)l * stride + m4];
        *(float4*)&vss[l][m4] = *(const float4*)&V[base + (size_t)l * stride + m4];
    }
    __syncthreads();

    const int g = tid >> 6;
    const int d = tid & 63;
    float S[16];
#pragma unroll
    for (int j = 0; j < 16; j++) S[j] = 0.f;
    for (int l = 0; l < CT; l++) {
        float vd = vss[l][d];
        float kf[16];
#pragma unroll
        for (int jj = 0; jj < 4; jj++)
            *(float4*)&kf[jj * 4] = *(const float4*)&kss[l][g * 16 + jj * 4];
#pragma unroll
        for (int j = 0; j < 16; j++) S[j] = fmaf(kf[j], vd, S[j]);
    }
    float* out = kv + ((size_t)(bh * NC + c) * MM) * MM;
#pragma unroll
    for (int j = 0; j < 16; j++)
        out[(size_t)(g * 16 + j) * 64 + d] = S[j];
    if (tid < 64) {
        float s = 0.f;
        for (int l = 0; l < CT; l++) s += kss[l][tid];
        ks[(size_t)(bh * NC + c) * MM + tid] = s;
    }
}

// ---------------------------------------------------------------------------
// prefix over chunks
// ---------------------------------------------------------------------------
__global__ __launch_bounds__(256)
void prefix_kernel(float* __restrict__ kv, float* __restrict__ ks)
{
    const int dg = blockIdx.x;
    const int bh = blockIdx.y;
    const int tid = threadIdx.x;
    const int m = tid >> 2;
    const int d = dg * 16 + (tid & 3) * 4;
    float4 run = make_float4(0.f, 0.f, 0.f, 0.f);
    for (int c = 0; c < NC; c++) {
        float* p = kv + ((size_t)(bh * NC + c) * MM + m) * MM + d;
        float4 val = *(float4*)p;
        *(float4*)p = run;
        run.x += val.x; run.y += val.y; run.z += val.z; run.w += val.w;
    }
    if (dg == 0 && tid < 64) {
        float r = 0.f;
        for (int c = 0; c < NC; c++) {
            float* p = ks + (size_t)(bh * NC + c) * MM + tid;
            float v = *p;
            *p = r;
            r += v;
        }
    }
}

// ---------------------------------------------------------------------------
// chunk_attn: writes bf16 hi/lo output (feeds the output projection GEMM)
// ---------------------------------------------------------------------------
#define PAD 68
__global__ __launch_bounds__(256)
void chunk_attn_kernel(const float* __restrict__ Q, const float* __restrict__ Kp,
                       const float* __restrict__ V, const float* __restrict__ kv,
                       const float* __restrict__ ksum,
                       __nv_bfloat16* __restrict__ Oh, __nv_bfloat16* __restrict__ Ol)
{
    extern __shared__ float sm[];
    float* Qt   = sm;
    float* Kt   = Qt + 64 * PAD;
    float* Vs   = Kt + 64 * PAD;
    float* Sp   = Vs + 64 * PAD;
    float* At   = Sp + 64 * PAD;
    float* zpre = At + 64 * PAD;
    float* den  = zpre + 64;

    const int c  = blockIdx.x;
    const int bh = blockIdx.y;
    const int b = bh >> 4, h = bh & 15;
    const int tid = threadIdx.x;
    const size_t base = ((size_t)(b * LL + c * CT) * HH + h) * MM;
    const size_t stride = HH * MM;

    for (int i = tid; i < 64 * 16; i += 256) {
        int r = i >> 4, m4 = (i & 15) * 4;
        float4 q = *(const float4*)&Q[base + (size_t)r * stride + m4];
        Qt[(m4 + 0) * PAD + r] = q.x; Qt[(m4 + 1) * PAD + r] = q.y;
        Qt[(m4 + 2) * PAD + r] = q.z; Qt[(m4 + 3) * PAD + r] = q.w;
        float4 k = *(const float4*)&Kp[base + (size_t)r * stride + m4];
        Kt[(m4 + 0) * PAD + r] = k.x; Kt[(m4 + 1) * PAD + r] = k.y;
        Kt[(m4 + 2) * PAD + r] = k.z; Kt[(m4 + 3) * PAD + r] = k.w;
        *(float4*)&Vs[r * PAD + m4] = *(const float4*)&V[base + (size_t)r * stride + m4];
        *(float4*)&Sp[r * PAD + m4] =
            *(const float4*)&kv[((size_t)(bh * NC + c) * MM + r) * MM + m4];
    }
    if (tid < 64) zpre[tid] = ksum[(size_t)(bh * NC + c) * MM + tid];
    __syncthreads();

    const int ty = tid >> 4;
    const int tx = tid & 15;
    const int r0 = ty * 4, c0 = tx * 4;

    float a[4][4];
#pragma unroll
    for (int i = 0; i < 4; i++)
#pragma unroll
        for (int j = 0; j < 4; j++) a[i][j] = 0.f;
    for (int m = 0; m < 64; m++) {
        float4 qv = *(float4*)&Qt[m * PAD + r0];
        float4 kv4 = *(float4*)&Kt[m * PAD + c0];
        float qf[4] = {qv.x, qv.y, qv.z, qv.w};
        float kf[4] = {kv4.x, kv4.y, kv4.z, kv4.w};
#pragma unroll
        for (int i = 0; i < 4; i++)
#pragma unroll
            for (int j = 0; j < 4; j++)
                a[i][j] = fmaf(qf[i], kf[j], a[i][j]);
    }
#pragma unroll
    for (int j = 0; j < 4; j++)
#pragma unroll
        for (int i = 0; i < 4; i++)
            At[(c0 + j) * PAD + (r0 + i)] = (c0 + j <= r0 + i) ? a[i][j] : 0.f;
    __syncthreads();

    if (tid < 64) {
        int r = tid;
        float s = 0.f;
        for (int cc = 0; cc < 64; cc++) s += At[cc * PAD + r];
        for (int m = 0; m < 64; m++) s = fmaf(Qt[m * PAD + r], zpre[m], s);
        den[r] = s;
    }

    float o[4][4];
#pragma unroll
    for (int i = 0; i < 4; i++)
#pragma unroll
        for (int j = 0; j < 4; j++) o[i][j] = 0.f;
    for (int cc = 0; cc < 64; cc++) {
        float4 av = *(float4*)&At[cc * PAD + r0];
        float4 vv = *(float4*)&Vs[cc * PAD + c0];
        float af[4] = {av.x, av.y, av.z, av.w};
        float vf[4] = {vv.x, vv.y, vv.z, vv.w};
#pragma unroll
        for (int i = 0; i < 4; i++)
#pragma unroll
            for (int j = 0; j < 4; j++)
                o[i][j] = fmaf(af[i], vf[j], o[i][j]);
    }
    for (int m = 0; m < 64; m++) {
        float4 qv = *(float4*)&Qt[m * PAD + r0];
        float4 sv = *(float4*)&Sp[m * PAD + c0];
        float qf[4] = {qv.x, qv.y, qv.z, qv.w};
        float sf[4] = {sv.x, sv.y, sv.z, sv.w};
#pragma unroll
        for (int i = 0; i < 4; i++)
#pragma unroll
            for (int j = 0; j < 4; j++)
                o[i][j] = fmaf(qf[i], sf[j], o[i][j]);
    }
    __syncthreads();

#pragma unroll
    for (int i = 0; i < 4; i++) {
        float dinv = 1.f / den[r0 + i];
        size_t idx = base + (size_t)(r0 + i) * stride + c0;
        __nv_bfloat16 hh[4], ll[4];
#pragma unroll
        for (int j = 0; j < 4; j++) {
            float val = o[i][j] * dinv;
            hh[j] = __float2bfloat16(val);
            ll[j] = __float2bfloat16(val - __bfloat162float(hh[j]));
        }
        __nv_bfloat162* ph = (__nv_bfloat162*)(Oh + idx);
        ph[0] = __halves2bfloat162(hh[0], hh[1]);
        ph[1] = __halves2bfloat162(hh[2], hh[3]);
        __nv_bfloat162* pl = (__nv_bfloat162*)(Ol + idx);
        pl[0] = __halves2bfloat162(ll[0], ll[1]);
        pl[1] = __halves2bfloat162(ll[2], ll[3]);
    }
}

// ---------------------------------------------------------------------------
// Launch
// ---------------------------------------------------------------------------
extern "C" void kernel_launch(void* const* d_in, const int* in_sizes, int n_in,
                              void* d_out, int out_size)
{
    const float* queries = (const float*)d_in[0];
    const float* keys    = (const float*)d_in[1];
    const float* values  = (const float*)d_in[2];
    const float* Wq = (const float*)d_in[3];
    const float* bq = (const float*)d_in[4];
    const float* Wk = (const float*)d_in[5];
    const float* bk = (const float*)d_in[6];
    const float* Wv = (const float*)d_in[7];
    const float* bv = (const float*)d_in[8];
    const float* Wo = (const float*)d_in[9];
    const float* bo = (const float*)d_in[10];
    const float* Wfq = (const float*)d_in[11];
    const float* Wfk = (const float*)d_in[12];
    float* out = (float*)d_out;

    float *gq, *gk, *gv, *gkm, *gkp, *gkv, *gks;
    __nv_bfloat16 *gxh, *gxl, *goh, *gol, *gwh, *gwl;
    cudaGetSymbolAddress((void**)&gq, g_q);
    cudaGetSymbolAddress((void**)&gk, g_k);
    cudaGetSymbolAddress((void**)&gv, g_v);
    cudaGetSymbolAddress((void**)&gkm, g_kmax);
    cudaGetSymbolAddress((void**)&gkp, g_kpart);
    cudaGetSymbolAddress((void**)&gkv, g_kv);
    cudaGetSymbolAddress((void**)&gks, g_ks);
    cudaGetSymbolAddress((void**)&gxh, g_xh);
    cudaGetSymbolAddress((void**)&gxl, g_xl);
    cudaGetSymbolAddress((void**)&goh, g_oh);
    cudaGetSymbolAddress((void**)&gol, g_ol);
    cudaGetSymbolAddress((void**)&gwh, g_wh);
    cudaGetSymbolAddress((void**)&gwl, g_wl);

    const size_t WSZ = (size_t)DMODEL * DMODEL;  // 1M
    const size_t XSZ = (size_t)MROWS * DMODEL;   // 8M

    // weight transpose + split
    dim3 wtg(32, 32);
    wt_cvt_kernel<<<wtg, 256>>>(Wq, gwh,           gwl);
    wt_cvt_kernel<<<wtg, 256>>>(Wk, gwh + WSZ,     gwl + WSZ);
    wt_cvt_kernel<<<wtg, 256>>>(Wv, gwh + 2 * WSZ, gwl + 2 * WSZ);
    wt_cvt_kernel<<<wtg, 256>>>(Wo, gwh + 3 * WSZ, gwl + 3 * WSZ);

    // input split
    const int cvtb = (int)(XSZ / 1024);
    cvt_hl_kernel<<<cvtb, 256>>>(queries, gxh,           gxl);
    cvt_hl_kernel<<<cvtb, 256>>>(keys,    gxh + XSZ,     gxl + XSZ);
    cvt_hl_kernel<<<cvtb, 256>>>(values,  gxh + 2 * XSZ, gxl + 2 * XSZ);

    // HMMA projections
    cudaFuncSetAttribute(gemm_bf16x3, cudaFuncAttributeMaxDynamicSharedMemorySize, GM_SMEM);
    dim3 gg(DMODEL / 128, MROWS / 128);  // (8, 64)
    gemm_bf16x3<<<gg, 256, GM_SMEM>>>(gxh,           gxl,           gwh,           gwl,           bq, gq);
    gemm_bf16x3<<<gg, 256, GM_SMEM>>>(gxh + XSZ,     gxl + XSZ,     gwh + WSZ,     gwl + WSZ,     bk, gk);
    gemm_bf16x3<<<gg, 256, GM_SMEM>>>(gxh + 2 * XSZ, gxl + 2 * XSZ, gwh + 2 * WSZ, gwl + 2 * WSZ, bv, gv);

    // key global max
    kmax_part_kernel<<<dim3(16, NBH), 256>>>(gk, gkp);
    kmax_final_kernel<<<NBH, 16>>>(gkp, gkm);

    // FAVOR feature maps
    favor_kernel<<<NROWS / 64, 512>>>(gq, Wfq, gkm, 1);
    favor_kernel<<<NROWS / 64, 512>>>(gk, Wfk, gkm, 0);

    // chunked causal linear attention
    chunk_sum_kernel<<<dim3(NC, NBH), 256>>>(gk, gv, gkv, gks);
    prefix_kernel<<<dim3(4, NBH), 256>>>(gkv, gks);

    static const int attn_smem = (5 * 64 * PAD + 128) * sizeof(float);
    cudaFuncSetAttribute(chunk_attn_kernel,
                         cudaFuncAttributeMaxDynamicSharedMemorySize, attn_smem);
    chunk_attn_kernel<<<dim3(NC, NBH), 256, attn_smem>>>(gq, gk, gv, gkv, gks, goh, gol);

    // output projection
    gemm_bf16x3<<<gg, 256, GM_SMEM>>>(goh, gol, gwh + 3 * WSZ, gwl + 3 * WSZ, bo, out);
}

// round 5
// speedup vs baseline: 4.2961x; 1.0446x over previous
#include <cuda_runtime.h>
#include <cuda_bf16.h>
#include <math.h>
#include <stdint.h>

// Problem constants (fixed by the dataset)
#define BB   2
#define LL   4096
#define HH   16
#define MM   64
#define DMODEL 1024
#define NROWS (BB*LL*HH)
#define DN    0.3535533905932738f
#define DIAGC 0.0625f
#define INVSQRTM 0.125f

#define CT   64
#define NC   (LL/CT)
#define NBH  (BB*HH)
#define MROWS (BB*LL)             // 8192

// ---------------------------------------------------------------------------
// scratch
// ---------------------------------------------------------------------------
__device__ float g_q[MROWS*DMODEL];
__device__ float g_k[MROWS*DMODEL];
__device__ float g_v[MROWS*DMODEL];
__device__ float g_kmax[NBH];
__device__ float g_kpart[NBH*16];
__device__ float g_kv[NBH*NC*MM*MM];
__device__ float g_ks[NBH*NC*MM];
__device__ __align__(16) __nv_bfloat16 g_xh[3*MROWS*DMODEL];
__device__ __align__(16) __nv_bfloat16 g_xl[3*MROWS*DMODEL];
__device__ __align__(16) __nv_bfloat16 g_oh[MROWS*DMODEL];
__device__ __align__(16) __nv_bfloat16 g_ol[MROWS*DMODEL];
__device__ __align__(16) __nv_bfloat16 g_wh[4*DMODEL*DMODEL];
__device__ __align__(16) __nv_bfloat16 g_wl[4*DMODEL*DMODEL];

// ---------------------------------------------------------------------------
// helpers (portable: compute_80+ features only; NO tcgen05)
// ---------------------------------------------------------------------------
__device__ __forceinline__ uint32_t smem_to_u32(const void* p) {
    uint32_t a;
    asm("{ .reg .u64 t; cvta.to.shared.u64 t, %1; cvt.u32.u64 %0, t; }"
        : "=r"(a) : "l"(p));
    return a;
}
#define SWZ64(b) ((b) ^ (((b) >> 3) & 0x30))

__device__ __forceinline__ void cp16(uint32_t dst, const void* src) {
    asm volatile("cp.async.cg.shared.global [%0], [%1], 16;" :: "r"(dst), "l"(src));
}
__device__ __forceinline__ void cp_commit() {
    asm volatile("cp.async.commit_group;" ::: "memory");
}
template<int N> __device__ __forceinline__ void cp_wait() {
    asm volatile("cp.async.wait_group %0;" :: "n"(N) : "memory");
}
__device__ __forceinline__ void ldsm4(uint32_t (&r)[4], uint32_t addr) {
    asm volatile("ldmatrix.sync.aligned.m8n8.x4.shared.b16 {%0,%1,%2,%3}, [%4];"
        : "=r"(r[0]), "=r"(r[1]), "=r"(r[2]), "=r"(r[3]) : "r"(addr));
}
__device__ __forceinline__ void mma16816(float (&d)[4], const uint32_t (&a)[4],
                                         const uint32_t* b) {
    asm volatile("mma.sync.aligned.m16n8k16.row.col.f32.bf16.bf16.f32 "
        "{%0,%1,%2,%3}, {%4,%5,%6,%7}, {%8,%9}, {%0,%1,%2,%3};"
        : "+f"(d[0]), "+f"(d[1]), "+f"(d[2]), "+f"(d[3])
        : "r"(a[0]), "r"(a[1]), "r"(a[2]), "r"(a[3]), "r"(b[0]), "r"(b[1]));
}

// ---------------------------------------------------------------------------
// bf16x3 HMMA GEMM (batched over grid.z):
//   C = (Ah+Al)[8192,1024] @ (Bh+Bl)^T + bias, C = Ah*Bh + Ah*Bl + Al*Bh
//   CTA tile 128x128, K-chunk 32 (64B rows, SW64), 2-stage cp.async,
//   smem 64KB -> 2 CTAs/SM.
// ---------------------------------------------------------------------------
#define GM_TILE  8192                   // 128 rows x 32 bf16 (64B) = 8KB
#define GM_STAGE (4*GM_TILE)            // Ah,Al,Bh,Bl = 32KB
#define GM_SMEM  (2*GM_STAGE)           // 64KB
#define GM_NKC   32

struct GemmBatch {
    const __nv_bfloat16 *Ah[3], *Al[3], *Bh[3], *Bl[3];
    const float* bias[3];
    float* C[3];
};

__device__ __forceinline__ void gm_cp_chunk(
    uint32_t stage,
    const __nv_bfloat16* Ah, const __nv_bfloat16* Al,
    const __nv_bfloat16* Bh, const __nv_bfloat16* Bl,
    int bm, int bn, int kc, int r_lo, int cb)
{
    const size_t ko = (size_t)kc * 64 + cb;   // bytes along k
#pragma unroll
    for (int j = 0; j < 2; j++) {
        const int row = r_lo + 64 * j;
        const uint32_t swz = SWZ64((uint32_t)(row * 64 + cb));
        cp16(stage + 0 * GM_TILE + swz, (const char*)Ah + (size_t)(bm + row) * 2048 + ko);
        cp16(stage + 1 * GM_TILE + swz, (const char*)Al + (size_t)(bm + row) * 2048 + ko);
        cp16(stage + 2 * GM_TILE + swz, (const char*)Bh + (size_t)(bn + row) * 2048 + ko);
        cp16(stage + 3 * GM_TILE + swz, (const char*)Bl + (size_t)(bn + row) * 2048 + ko);
    }
    cp_commit();
}

__device__ __forceinline__ void gm_compute(uint32_t st, int wm, int wn, int lid,
                                           float acc[2][8][4])
{
    const int ar  = wm + (lid & 15);
    const int akb = (lid >> 4) * 16;
    const int br  = (lid & 7) + ((lid >> 4) << 3);
    const int bkb = ((lid >> 3) & 1) * 16;
#pragma unroll
    for (int k0 = 0; k0 < 2; k0++) {
        const int kb = k0 * 32;      // 16 k-elems = 32B per step
        const uint32_t a0off = SWZ64((uint32_t)(ar * 64 + kb + akb));
        const uint32_t a1off = SWZ64((uint32_t)((ar + 16) * 64 + kb + akb));
        uint32_t ah[2][4], al[2][4];
        ldsm4(ah[0], st + a0off);
        ldsm4(ah[1], st + a1off);
        ldsm4(al[0], st + GM_TILE + a0off);
        ldsm4(al[1], st + GM_TILE + a1off);
#pragma unroll
        for (int g = 0; g < 4; g++) {
            const uint32_t boff = SWZ64((uint32_t)((wn + g * 16 + br) * 64 + kb + bkb));
            uint32_t bh[4], bl[4];
            ldsm4(bh, st + 2 * GM_TILE + boff);
            ldsm4(bl, st + 3 * GM_TILE + boff);
#pragma unroll
            for (int mt = 0; mt < 2; mt++) {
                mma16816(acc[mt][2 * g],     ah[mt], &bh[0]);
                mma16816(acc[mt][2 * g + 1], ah[mt], &bh[2]);
                mma16816(acc[mt][2 * g],     ah[mt], &bl[0]);
                mma16816(acc[mt][2 * g + 1], ah[mt], &bl[2]);
                mma16816(acc[mt][2 * g],     al[mt], &bh[0]);
                mma16816(acc[mt][2 * g + 1], al[mt], &bh[2]);
            }
        }
    }
}

__global__ __launch_bounds__(256, 2)
void gemm_bf16x3(GemmBatch batch)
{
    extern __shared__ char smem[];
    const uint32_t sb = smem_to_u32(smem);
    const int tid = threadIdx.x;
    const int wid = tid >> 5, lid = tid & 31;
    const int gz = blockIdx.z;
    const __nv_bfloat16* Ah = batch.Ah[gz];
    const __nv_bfloat16* Al = batch.Al[gz];
    const __nv_bfloat16* Bh = batch.Bh[gz];
    const __nv_bfloat16* Bl = batch.Bl[gz];
    const float* bias = batch.bias[gz];
    float* C = batch.C[gz];

    const int bn = blockIdx.x * 128;
    const int bm = blockIdx.y * 128;
    const int r_lo = tid >> 2;           // 0..63
    const int cb = (tid & 3) * 16;       // 0..48
    const int wm = (wid & 3) * 32;
    const int wn = (wid >> 2) * 64;

    float acc[2][8][4];
#pragma unroll
    for (int mt = 0; mt < 2; mt++)
#pragma unroll
        for (int nt = 0; nt < 8; nt++)
#pragma unroll
            for (int j = 0; j < 4; j++) acc[mt][nt][j] = 0.f;

    gm_cp_chunk(sb,            Ah, Al, Bh, Bl, bm, bn, 0, r_lo, cb);
    gm_cp_chunk(sb + GM_STAGE, Ah, Al, Bh, Bl, bm, bn, 1, r_lo, cb);

    for (int i = 0; i < GM_NKC; i++) {
        if (i < GM_NKC - 2) cp_wait<1>(); else cp_wait<0>();
        __syncthreads();
        gm_compute(sb + (uint32_t)(i & 1) * GM_STAGE, wm, wn, lid, acc);
        __syncthreads();
        if (i + 2 < GM_NKC)
            gm_cp_chunk(sb + (uint32_t)(i & 1) * GM_STAGE,
                        Ah, Al, Bh, Bl, bm, bn, i + 2, r_lo, cb);
    }

    // epilogue: bias + write fp32
    const int row_b = bm + wm + (lid >> 2);
    const int col_b = bn + wn + (lid & 3) * 2;
#pragma unroll
    for (int mt = 0; mt < 2; mt++) {
#pragma unroll
        for (int nt = 0; nt < 8; nt++) {
            const int col = col_b + nt * 8;
            const float b0 = bias[col], b1 = bias[col + 1];
            const int r0 = row_b + mt * 16;
            float2 v0, v1;
            v0.x = acc[mt][nt][0] + b0; v0.y = acc[mt][nt][1] + b1;
            v1.x = acc[mt][nt][2] + b0; v1.y = acc[mt][nt][3] + b1;
            *(float2*)&C[(size_t)r0 * DMODEL + col] = v0;
            *(float2*)&C[(size_t)(r0 + 8) * DMODEL + col] = v1;
        }
    }
}

// ---------------------------------------------------------------------------
// fp32 -> bf16 hi/lo split (batched over grid.y)
// ---------------------------------------------------------------------------
struct CvtBatch { const float* x[3]; __nv_bfloat16 *h[3], *l[3]; };

__global__ __launch_bounds__(256)
void cvt_hl_kernel(CvtBatch batch)
{
    const float* x = batch.x[blockIdx.y];
    __nv_bfloat16* h = batch.h[blockIdx.y];
    __nv_bfloat16* l = batch.l[blockIdx.y];
    const int i = (blockIdx.x * 256 + threadIdx.x) * 4;
    float4 v = *(const float4*)(x + i);
    __nv_bfloat16 h0 = __float2bfloat16(v.x), h1 = __float2bfloat16(v.y);
    __nv_bfloat16 h2 = __float2bfloat16(v.z), h3 = __float2bfloat16(v.w);
    __nv_bfloat16 l0 = __float2bfloat16(v.x - __bfloat162float(h0));
    __nv_bfloat16 l1 = __float2bfloat16(v.y - __bfloat162float(h1));
    __nv_bfloat16 l2 = __float2bfloat16(v.z - __bfloat162float(h2));
    __nv_bfloat16 l3 = __float2bfloat16(v.w - __bfloat162float(h3));
    __nv_bfloat162* ph = (__nv_bfloat162*)(h + i);
    ph[0] = __halves2bfloat162(h0, h1); ph[1] = __halves2bfloat162(h2, h3);
    __nv_bfloat162* pl = (__nv_bfloat162*)(l + i);
    pl[0] = __halves2bfloat162(l0, l1); pl[1] = __halves2bfloat162(l2, l3);
}

// ---------------------------------------------------------------------------
// weight transpose + hi/lo split (batched over grid.z)
// ---------------------------------------------------------------------------
struct WtBatch { const float* W[4]; __nv_bfloat16 *Th[4], *Tl[4]; };

__global__ __launch_bounds__(256)
void wt_cvt_kernel(WtBatch batch)
{
    __shared__ float t[32][33];
    const float* W = batch.W[blockIdx.z];
    __nv_bfloat16* Th = batch.Th[blockIdx.z];
    __nv_bfloat16* Tl = batch.Tl[blockIdx.z];
    const int kx = blockIdx.x * 32;
    const int nx = blockIdx.y * 32;
    const int tx = threadIdx.x & 31, ty = threadIdx.x >> 5;
    for (int r = ty; r < 32; r += 8)
        t[r][tx] = W[(size_t)(kx + r) * DMODEL + nx + tx];
    __syncthreads();
    for (int r = ty; r < 32; r += 8) {
        float v = t[tx][r];
        __nv_bfloat16 h = __float2bfloat16(v);
        __nv_bfloat16 lo = __float2bfloat16(v - __bfloat162float(h));
        Th[(size_t)(nx + r) * DMODEL + kx + tx] = h;
        Tl[(size_t)(nx + r) * DMODEL + kx + tx] = lo;
    }
}

// ---------------------------------------------------------------------------
// kmax (two stage)
// ---------------------------------------------------------------------------
__global__ void kmax_part_kernel(const float* __restrict__ Kp, float* __restrict__ kpart)
{
    const int bh = blockIdx.y, sl = blockIdx.x;
    const int b = bh >> 4, h = bh & 15;
    const int tid = threadIdx.x;
    float m = -1e30f;
    const int l0 = sl * 256;
    for (int idx = tid; idx < 256 * MM; idx += 256) {
        int l = l0 + (idx >> 6), mm = idx & 63;
        m = fmaxf(m, Kp[((size_t)(b * LL + l) * HH + h) * MM + mm]);
    }
    __shared__ float red[256];
    red[tid] = m;
    __syncthreads();
    for (int s = 128; s > 0; s >>= 1) {
        if (tid < s) red[tid] = fmaxf(red[tid], red[tid + s]);
        __syncthreads();
    }
    if (tid == 0) kpart[bh * 16 + sl] = red[0];
}

__global__ void kmax_final_kernel(const float* __restrict__ kpart, float* __restrict__ kmax)
{
    const int bh = blockIdx.x;
    const int t = threadIdx.x;
    __shared__ float red[16];
    red[t] = kpart[bh * 16 + t];
    __syncthreads();
    if (t < 8) red[t] = fmaxf(red[t], red[t + 8]);
    __syncthreads();
    if (t < 4) red[t] = fmaxf(red[t], red[t + 4]);
    __syncthreads();
    if (t == 0) kmax[bh] = DN * fmaxf(fmaxf(red[0], red[1]), fmaxf(red[2], red[3]));
}

// ---------------------------------------------------------------------------
// FAVOR feature map (in-place), batched over grid.y (0 = query, 1 = key)
// ---------------------------------------------------------------------------
__global__ __launch_bounds__(512)
void favor_kernel(float* __restrict__ Xq, float* __restrict__ Xk,
                  const float* __restrict__ Wfq, const float* __restrict__ Wfk,
                  const float* __restrict__ kmax)
{
    __shared__ float Wt[64][65];
    __shared__ float xs[8][64];
    const int is_query = (blockIdx.y == 0);
    float* X = is_query ? Xq : Xk;
    const float* Wf = is_query ? Wfq : Wfk;

    const int tid = threadIdx.x;
    for (int i = tid; i < 64 * 64; i += 512) {
        int d = i >> 6, m = i & 63;
        Wt[m][d] = Wf[i];
    }
    __syncthreads();
    const int r = tid >> 6;
    const int d = tid & 63;
    for (int pass = 0; pass < 8; pass++) {
        int row = blockIdx.x * 64 + pass * 8 + r;
        xs[r][d] = DN * X[(size_t)row * 64 + d];
        __syncthreads();
        float dot = 0.f, ss = 0.f, mx = -1e30f;
#pragma unroll 8
        for (int m = 0; m < 64; m++) {
            float x = xs[r][m];
            dot = fmaf(Wt[m][d], x, dot);
            ss  = fmaf(x, x, ss);
            mx  = fmaxf(mx, x);
        }
        float mq;
        if (is_query) mq = mx;
        else {
            int h = row & 15;
            int b = row >> 16;
            mq = kmax[b * HH + h];
        }
        float phi = INVSQRTM * __expf(dot - DIAGC * ss - mq + 1e-8f);
        __syncthreads();
        X[(size_t)row * 64 + d] = phi;
    }
}

// ---------------------------------------------------------------------------
// chunk_sum
// ---------------------------------------------------------------------------
__global__ __launch_bounds__(256)
void chunk_sum_kernel(const float* __restrict__ Kp, const float* __restrict__ V,
                      float* __restrict__ kv, float* __restrict__ ks)
{
    __shared__ __align__(16) float kss[CT][64];
    __shared__ __align__(16) float vss[CT][64];
    const int c  = blockIdx.x;
    const int bh = blockIdx.y;
    const int b = bh >> 4, h = bh & 15;
    const int tid = threadIdx.x;
    const size_t base = ((size_t)(b * LL + c * CT) * HH + h) * MM;
    const size_t stride = HH * MM;

    for (int i = tid; i < CT * 16; i += 256) {
        int l = i >> 4, m4 = (i & 15) * 4;
        *(float4*)&kss[l][m4] = *(const float4*)&Kp[base + (size_t)l * stride + m4];
        *(float4*)&vss[l][m4] = *(const float4*)&V[base + (size_t)l * stride + m4];
    }
    __syncthreads();

    const int g = tid >> 6;
    const int d = tid & 63;
    float S[16];
#pragma unroll
    for (int j = 0; j < 16; j++) S[j] = 0.f;
    for (int l = 0; l < CT; l++) {
        float vd = vss[l][d];
        float kf[16];
#pragma unroll
        for (int jj = 0; jj < 4; jj++)
            *(float4*)&kf[jj * 4] = *(const float4*)&kss[l][g * 16 + jj * 4];
#pragma unroll
        for (int j = 0; j < 16; j++) S[j] = fmaf(kf[j], vd, S[j]);
    }
    float* out = kv + ((size_t)(bh * NC + c) * MM) * MM;
#pragma unroll
    for (int j = 0; j < 16; j++)
        out[(size_t)(g * 16 + j) * 64 + d] = S[j];
    if (tid < 64) {
        float s = 0.f;
        for (int l = 0; l < CT; l++) s += kss[l][tid];
        ks[(size_t)(bh * NC + c) * MM + tid] = s;
    }
}

// ---------------------------------------------------------------------------
// prefix over chunks
// ---------------------------------------------------------------------------
__global__ __launch_bounds__(256)
void prefix_kernel(float* __restrict__ kv, float* __restrict__ ks)
{
    const int dg = blockIdx.x;
    const int bh = blockIdx.y;
    const int tid = threadIdx.x;
    const int m = tid >> 2;
    const int d = dg * 16 + (tid & 3) * 4;
    float4 run = make_float4(0.f, 0.f, 0.f, 0.f);
    for (int c = 0; c < NC; c++) {
        float* p = kv + ((size_t)(bh * NC + c) * MM + m) * MM + d;
        float4 val = *(float4*)p;
        *(float4*)p = run;
        run.x += val.x; run.y += val.y; run.z += val.z; run.w += val.w;
    }
    if (dg == 0 && tid < 64) {
        float r = 0.f;
        for (int c = 0; c < NC; c++) {
            float* p = ks + (size_t)(bh * NC + c) * MM + tid;
            float v = *p;
            *p = r;
            r += v;
        }
    }
}

// ---------------------------------------------------------------------------
// chunk_attn: writes bf16 hi/lo output (feeds the output projection GEMM)
// ---------------------------------------------------------------------------
#define PAD 68
__global__ __launch_bounds__(256)
void chunk_attn_kernel(const float* __restrict__ Q, const float* __restrict__ Kp,
                       const float* __restrict__ V, const float* __restrict__ kv,
                       const float* __restrict__ ksum,
                       __nv_bfloat16* __restrict__ Oh, __nv_bfloat16* __restrict__ Ol)
{
    extern __shared__ float sm[];
    float* Qt   = sm;
    float* Kt   = Qt + 64 * PAD;
    float* Vs   = Kt + 64 * PAD;
    float* Sp   = Vs + 64 * PAD;
    float* At   = Sp + 64 * PAD;
    float* zpre = At + 64 * PAD;
    float* den  = zpre + 64;

    const int c  = blockIdx.x;
    const int bh = blockIdx.y;
    const int b = bh >> 4, h = bh & 15;
    const int tid = threadIdx.x;
    const size_t base = ((size_t)(b * LL + c * CT) * HH + h) * MM;
    const size_t stride = HH * MM;

    for (int i = tid; i < 64 * 16; i += 256) {
        int r = i >> 4, m4 = (i & 15) * 4;
        float4 q = *(const float4*)&Q[base + (size_t)r * stride + m4];
        Qt[(m4 + 0) * PAD + r] = q.x; Qt[(m4 + 1) * PAD + r] = q.y;
        Qt[(m4 + 2) * PAD + r] = q.z; Qt[(m4 + 3) * PAD + r] = q.w;
        float4 k = *(const float4*)&Kp[base + (size_t)r * stride + m4];
        Kt[(m4 + 0) * PAD + r] = k.x; Kt[(m4 + 1) * PAD + r] = k.y;
        Kt[(m4 + 2) * PAD + r] = k.z; Kt[(m4 + 3) * PAD + r] = k.w;
        *(float4*)&Vs[r * PAD + m4] = *(const float4*)&V[base + (size_t)r * stride + m4];
        *(float4*)&Sp[r * PAD + m4] =
            *(const float4*)&kv[((size_t)(bh * NC + c) * MM + r) * MM + m4];
    }
    if (tid < 64) zpre[tid] = ksum[(size_t)(bh * NC + c) * MM + tid];
    __syncthreads();

    const int ty = tid >> 4;
    const int tx = tid & 15;
    const int r0 = ty * 4, c0 = tx * 4;

    float a[4][4];
#pragma unroll
    for (int i = 0; i < 4; i++)
#pragma unroll
        for (int j = 0; j < 4; j++) a[i][j] = 0.f;
    for (int m = 0; m < 64; m++) {
        float4 qv = *(float4*)&Qt[m * PAD + r0];
        float4 kv4 = *(float4*)&Kt[m * PAD + c0];
        float qf[4] = {qv.x, qv.y, qv.z, qv.w};
        float kf[4] = {kv4.x, kv4.y, kv4.z, kv4.w};
#pragma unroll
        for (int i = 0; i < 4; i++)
#pragma unroll
            for (int j = 0; j < 4; j++)
                a[i][j] = fmaf(qf[i], kf[j], a[i][j]);
    }
#pragma unroll
    for (int j = 0; j < 4; j++)
#pragma unroll
        for (int i = 0; i < 4; i++)
            At[(c0 + j) * PAD + (r0 + i)] = (c0 + j <= r0 + i) ? a[i][j] : 0.f;
    __syncthreads();

    if (tid < 64) {
        int r = tid;
        float s = 0.f;
        for (int cc = 0; cc < 64; cc++) s += At[cc * PAD + r];
        for (int m = 0; m < 64; m++) s = fmaf(Qt[m * PAD + r], zpre[m], s);
        den[r] = s;
    }

    float o[4][4];
#pragma unroll
    for (int i = 0; i < 4; i++)
#pragma unroll
        for (int j = 0; j < 4; j++) o[i][j] = 0.f;
    for (int cc = 0; cc < 64; cc++) {
        float4 av = *(float4*)&At[cc * PAD + r0];
        float4 vv = *(float4*)&Vs[cc * PAD + c0];
        float af[4] = {av.x, av.y, av.z, av.w};
        float vf[4] = {vv.x, vv.y, vv.z, vv.w};
#pragma unroll
        for (int i = 0; i < 4; i++)
#pragma unroll
            for (int j = 0; j < 4; j++)
                o[i][j] = fmaf(af[i], vf[j], o[i][j]);
    }
    for (int m = 0; m < 64; m++) {
        float4 qv = *(float4*)&Qt[m * PAD + r0];
        float4 sv = *(float4*)&Sp[m * PAD + c0];
        float qf[4] = {qv.x, qv.y, qv.z, qv.w};
        float sf[4] = {sv.x, sv.y, sv.z, sv.w};
#pragma unroll
        for (int i = 0; i < 4; i++)
#pragma unroll
            for (int j = 0; j < 4; j++)
                o[i][j] = fmaf(qf[i], sf[j], o[i][j]);
    }
    __syncthreads();

#pragma unroll
    for (int i = 0; i < 4; i++) {
        float dinv = 1.f / den[r0 + i];
        size_t idx = base + (size_t)(r0 + i) * stride + c0;
        __nv_bfloat16 hh[4], ll[4];
#pragma unroll
        for (int j = 0; j < 4; j++) {
            float val = o[i][j] * dinv;
            hh[j] = __float2bfloat16(val);
            ll[j] = __float2bfloat16(val - __bfloat162float(hh[j]));
        }
        __nv_bfloat162* ph = (__nv_bfloat162*)(Oh + idx);
        ph[0] = __halves2bfloat162(hh[0], hh[1]);
        ph[1] = __halves2bfloat162(hh[2], hh[3]);
        __nv_bfloat162* pl = (__nv_bfloat162*)(Ol + idx);
        pl[0] = __halves2bfloat162(ll[0], ll[1]);
        pl[1] = __halves2bfloat162(ll[2], ll[3]);
    }
}

// ---------------------------------------------------------------------------
// Launch
// ---------------------------------------------------------------------------
extern "C" void kernel_launch(void* const* d_in, const int* in_sizes, int n_in,
                              void* d_out, int out_size)
{
    const float* queries = (const float*)d_in[0];
    const float* keys    = (const float*)d_in[1];
    const float* values  = (const float*)d_in[2];
    const float* Wq = (const float*)d_in[3];
    const float* bq = (const float*)d_in[4];
    const float* Wk = (const float*)d_in[5];
    const float* bk = (const float*)d_in[6];
    const float* Wv = (const float*)d_in[7];
    const float* bv = (const float*)d_in[8];
    const float* Wo = (const float*)d_in[9];
    const float* bo = (const float*)d_in[10];
    const float* Wfq = (const float*)d_in[11];
    const float* Wfk = (const float*)d_in[12];
    float* out = (float*)d_out;

    float *gq, *gk, *gv, *gkm, *gkp, *gkv, *gks;
    __nv_bfloat16 *gxh, *gxl, *goh, *gol, *gwh, *gwl;
    cudaGetSymbolAddress((void**)&gq, g_q);
    cudaGetSymbolAddress((void**)&gk, g_k);
    cudaGetSymbolAddress((void**)&gv, g_v);
    cudaGetSymbolAddress((void**)&gkm, g_kmax);
    cudaGetSymbolAddress((void**)&gkp, g_kpart);
    cudaGetSymbolAddress((void**)&gkv, g_kv);
    cudaGetSymbolAddress((void**)&gks, g_ks);
    cudaGetSymbolAddress((void**)&gxh, g_xh);
    cudaGetSymbolAddress((void**)&gxl, g_xl);
    cudaGetSymbolAddress((void**)&goh, g_oh);
    cudaGetSymbolAddress((void**)&gol, g_ol);
    cudaGetSymbolAddress((void**)&gwh, g_wh);
    cudaGetSymbolAddress((void**)&gwl, g_wl);

    const size_t WSZ = (size_t)DMODEL * DMODEL;  // 1M
    const size_t XSZ = (size_t)MROWS * DMODEL;   // 8M

    // weight transpose + split (batched)
    WtBatch wb;
    wb.W[0] = Wq; wb.W[1] = Wk; wb.W[2] = Wv; wb.W[3] = Wo;
    for (int i = 0; i < 4; i++) { wb.Th[i] = gwh + i * WSZ; wb.Tl[i] = gwl + i * WSZ; }
    wt_cvt_kernel<<<dim3(32, 32, 4), 256>>>(wb);

    // input split (batched)
    CvtBatch cb;
    cb.x[0] = queries; cb.x[1] = keys; cb.x[2] = values;
    for (int i = 0; i < 3; i++) { cb.h[i] = gxh + i * XSZ; cb.l[i] = gxl + i * XSZ; }
    cvt_hl_kernel<<<dim3((int)(XSZ / 1024), 3), 256>>>(cb);

    // HMMA projections (batched over grid.z)
    cudaFuncSetAttribute(gemm_bf16x3, cudaFuncAttributeMaxDynamicSharedMemorySize, GM_SMEM);
    GemmBatch gb;
    for (int i = 0; i < 3; i++) {
        gb.Ah[i] = gxh + i * XSZ; gb.Al[i] = gxl + i * XSZ;
        gb.Bh[i] = gwh + i * WSZ; gb.Bl[i] = gwl + i * WSZ;
    }
    gb.bias[0] = bq; gb.bias[1] = bk; gb.bias[2] = bv;
    gb.C[0] = gq; gb.C[1] = gk; gb.C[2] = gv;
    gemm_bf16x3<<<dim3(DMODEL / 128, MROWS / 128, 3), 256, GM_SMEM>>>(gb);

    // key global max
    kmax_part_kernel<<<dim3(16, NBH), 256>>>(gk, gkp);
    kmax_final_kernel<<<NBH, 16>>>(gkp, gkm);

    // FAVOR feature maps (q and k in one launch)
    favor_kernel<<<dim3(NROWS / 64, 2), 512>>>(gq, gk, Wfq, Wfk, gkm);

    // chunked causal linear attention
    chunk_sum_kernel<<<dim3(NC, NBH), 256>>>(gk, gv, gkv, gks);
    prefix_kernel<<<dim3(4, NBH), 256>>>(gkv, gks);

    static const int attn_smem = (5 * 64 * PAD + 128) * sizeof(float);
    cudaFuncSetAttribute(chunk_attn_kernel,
                         cudaFuncAttributeMaxDynamicSharedMemorySize, attn_smem);
    chunk_attn_kernel<<<dim3(NC, NBH), 256, attn_smem>>>(gq, gk, gv, gkv, gks, goh, gol);

    // output projection
    GemmBatch ob;
    ob.Ah[0] = goh; ob.Al[0] = gol;
    ob.Bh[0] = gwh + 3 * WSZ; ob.Bl[0] = gwl + 3 * WSZ;
    ob.bias[0] = bo; ob.C[0] = out;
    for (int i = 1; i < 3; i++) {
        ob.Ah[i] = goh; ob.Al[i] = gol; ob.Bh[i] = ob.Bh[0]; ob.Bl[i] = ob.Bl[0];
        ob.bias[i] = bo; ob.C[i] = out;
    }
    gemm_bf16x3<<<dim3(DMODEL / 128, MROWS / 128, 1), 256, GM_SMEM>>>(ob);
}